// round 10
// baseline (speedup 1.0000x reference)
#include <cuda_runtime.h>
#include <cstdint>

// ---------------------------------------------------------------------------
// Fused multi-head attention, one CTA per batch element.
//   x[4096,128,128] -> out[4096,128,128]
//   TF32 mma.sync (m16n8k8) for all 6 GEMM stages, fp32 accumulate.
//   8 warps; warp w owns query rows [16w, 16w+16).
//   R9: pair-interleaved SMEM layouts -> every MMA fragment is LDS.64;
//       shared-load instruction count halved.
//   Pair layout: element with contraction index k, other index n lives at
//     word = pslot(k)*ST + n*2 + half(k),  pslot(k)=(k>>3)*4+(k&3),
//     half(k)=(k>>2)&1.  All ST ≡ 8 (mod 32) -> conflict-free LDS.64.
// ---------------------------------------------------------------------------

namespace {

constexpr int XST = 136;   // x:  token-major rows, dim pairs (A frags)
constexpr int KST = 40;    // K:  token-major rows, dim pairs (S B frags)
constexpr int VST = 72;    // V:  token-pair rows,  dim cols  (PV B frags)
constexpr int W3T = 200;   // Wq|Wk|Wv packed: d-pair rows, 3*32 n cols
constexpr int OST = 136;   // O:  token-major rows, dim pairs (proj A frags)
constexpr int PST = 264;   // Wp: d-pair rows, 128 n cols     (proj B frags)

constexpr int XP_OFF = 0;
constexpr int KP_OFF = XP_OFF + 128 * XST;   // 17408
constexpr int VP_OFF = KP_OFF + 128 * KST;   // 22528
constexpr int WP_OFF = VP_OFF + 64 * VST;    // 27136
constexpr int OP_OFF = WP_OFF + 64 * W3T;    // 39936
constexpr int SMEM_WORDS = OP_OFF + 128 * OST;  // 57344 words = 229376 B
// Wp stage (64*264 = 16896 words) reuses offset 0 (XP dead by then).
constexpr unsigned SMEM_BYTES = SMEM_WORDS * 4;

__device__ __forceinline__ uint32_t f2tf32(float f) {
  uint32_t r;
  asm("cvt.rna.tf32.f32 %0, %1;" : "=r"(r) : "f"(f));
  return r;
}

__device__ __forceinline__ void mma8(float& d0, float& d1, float& d2, float& d3,
                                     uint32_t a0, uint32_t a1, uint32_t a2, uint32_t a3,
                                     uint32_t b0, uint32_t b1) {
  asm volatile(
      "mma.sync.aligned.m16n8k8.row.col.f32.tf32.tf32.f32 "
      "{%0,%1,%2,%3},{%4,%5,%6,%7},{%8,%9},{%0,%1,%2,%3};"
      : "+f"(d0), "+f"(d1), "+f"(d2), "+f"(d3)
      : "r"(a0), "r"(a1), "r"(a2), "r"(a3), "r"(b0), "r"(b1));
}

// m16n8 C-layout tile -> m16k8 A-layout tile (tf32). 8 shuffles, warp-uniform.
__device__ __forceinline__ void c2a(float c0, float c1, float c2, float c3,
                                    uint32_t a[4]) {
  int lane = threadIdx.x & 31;
  int qi = lane & 3;
  int s1 = (lane & ~3) | (qi >> 1);
  int s2 = s1 + 2;
  float t0 = __shfl_sync(0xffffffffu, c0, s1);
  float t1 = __shfl_sync(0xffffffffu, c1, s1);
  float t2 = __shfl_sync(0xffffffffu, c2, s1);
  float t3 = __shfl_sync(0xffffffffu, c3, s1);
  float u0 = __shfl_sync(0xffffffffu, c0, s2);
  float u1 = __shfl_sync(0xffffffffu, c1, s2);
  float u2 = __shfl_sync(0xffffffffu, c2, s2);
  float u3 = __shfl_sync(0xffffffffu, c3, s2);
  bool odd = (qi & 1);
  a[0] = f2tf32(odd ? t1 : t0);
  a[1] = f2tf32(odd ? t3 : t2);
  a[2] = f2tf32(odd ? u1 : u0);
  a[3] = f2tf32(odd ? u3 : u2);
}

__device__ __forceinline__ uint2 lds64(const uint32_t* p) {
  return *reinterpret_cast<const uint2*>(p);
}

__global__ __launch_bounds__(256, 1)
void mha_fused_kernel(const float* __restrict__ x,
                      const float* __restrict__ Wq, const float* __restrict__ bq,
                      const float* __restrict__ Wk, const float* __restrict__ bk,
                      const float* __restrict__ Wv, const float* __restrict__ bv,
                      const float* __restrict__ Wp, const float* __restrict__ bp,
                      float* __restrict__ out) {
  extern __shared__ uint32_t sm[];
  uint32_t* XP = sm + XP_OFF;
  uint32_t* KP = sm + KP_OFF;
  uint32_t* VP = sm + VP_OFF;
  uint32_t* WP = sm + WP_OFF;
  uint32_t* OP = sm + OP_OFF;

  const int tid = threadIdx.x;
  const int lane = tid & 31;
  const int w = tid >> 5;
  const int g = lane >> 2;
  const int qi = lane & 3;
  const int b = blockIdx.x;
  const int row0 = w * 16 + g;
  const int row1 = row0 + 8;
  // column slot within an 8-word pair block for C-frag cols (2qi, 2qi+1)
  const int t0 = ((qi & 1) << 2) + (qi >> 1);

  // ---- stage x -> XP (tf32, dim-pair interleaved) ----
  {
    const float4* xg = reinterpret_cast<const float4*>(x) + (size_t)b * 4096;
    #pragma unroll
    for (int i = 0; i < 16; i++) {
      int v = tid + i * 256;
      float4 f = xg[v];
      int t = v >> 5;
      int d0 = (v & 31) << 2;
      uint32_t* p = XP + t * XST + ((d0 >> 3) << 3) + ((d0 >> 2) & 1);
      p[0] = f2tf32(f.x); p[2] = f2tf32(f.y); p[4] = f2tf32(f.z); p[6] = f2tf32(f.w);
    }
  }

  const int nt_lim = 2 * w + 1;  // last active key tile under causal mask (warp-uniform)
  const float scale = 0.088388347648318447f;  // 128^-0.5 (CONTEXT_SIZE scaling!)

  #pragma unroll
  for (int h = 0; h < 4; h++) {
    __syncthreads();  // prior iteration's K/V/W reads complete

    // ---- stage Wq_h|Wk_h|Wv_h -> WP[64 d-pair rows][3*64 + pad] ----
    {
      const float4* wq4 = reinterpret_cast<const float4*>(Wq + h * 4096);
      const float4* wk4 = reinterpret_cast<const float4*>(Wk + h * 4096);
      const float4* wv4 = reinterpret_cast<const float4*>(Wv + h * 4096);
      #pragma unroll
      for (int i = 0; i < 4; i++) {
        int v = tid + i * 256;       // 0..1023 float4s per matrix
        int d = v >> 3;              // D index 0..127
        int n0 = (v & 7) << 2;       // col within 32
        int ps = ((d >> 3) << 2) + (d & 3);
        int hf = (d >> 2) & 1;
        uint32_t* p = WP + ps * W3T + (n0 << 1) + hf;
        float4 f;
        f = wq4[v];
        p[0] = f2tf32(f.x); p[2] = f2tf32(f.y); p[4] = f2tf32(f.z); p[6] = f2tf32(f.w);
        f = wk4[v];
        p[64] = f2tf32(f.x); p[66] = f2tf32(f.y); p[68] = f2tf32(f.z); p[70] = f2tf32(f.w);
        f = wv4[v];
        p[128] = f2tf32(f.x); p[130] = f2tf32(f.y); p[132] = f2tf32(f.z); p[134] = f2tf32(f.w);
      }
    }
    __syncthreads();

    // ---- Q,K,V = x @ W (+bias): shared A frags, 12 MMAs of ILP per kt ----
    float qacc[4][4], kacc[4][4], vacc[4][4];
    #pragma unroll
    for (int nt = 0; nt < 4; nt++) {
      #pragma unroll
      for (int j = 0; j < 4; j++) { qacc[nt][j] = 0.f; kacc[nt][j] = 0.f; vacc[nt][j] = 0.f; }
    }
    #pragma unroll
    for (int kt = 0; kt < 16; kt++) {
      int acol = (kt * 4 + qi) << 1;
      uint2 A0 = lds64(XP + row0 * XST + acol);   // (a0, a2)
      uint2 A1 = lds64(XP + row1 * XST + acol);   // (a1, a3)
      int brow = (kt * 4 + qi) * W3T;
      #pragma unroll
      for (int nt = 0; nt < 4; nt++) {
        int bcol = (nt * 8 + g) << 1;
        uint2 Bq = lds64(WP + brow + bcol);
        uint2 Bk = lds64(WP + brow + 64 + bcol);
        uint2 Bv = lds64(WP + brow + 128 + bcol);
        mma8(qacc[nt][0], qacc[nt][1], qacc[nt][2], qacc[nt][3],
             A0.x, A1.x, A0.y, A1.y, Bq.x, Bq.y);
        mma8(kacc[nt][0], kacc[nt][1], kacc[nt][2], kacc[nt][3],
             A0.x, A1.x, A0.y, A1.y, Bk.x, Bk.y);
        mma8(vacc[nt][0], vacc[nt][1], vacc[nt][2], vacc[nt][3],
             A0.x, A1.x, A0.y, A1.y, Bv.x, Bv.y);
      }
    }

    // ---- biases; K -> KP (dim pairs), V -> VP (token pairs); Q c2a ----
    uint32_t qa[4][4];
    const int vp0 = (8 * w + (g & 3)) * VST + ((g >> 2) & 1);  // row0 token slot
    #pragma unroll
    for (int nt = 0; nt < 4; nt++) {
      int c = nt * 8 + 2 * qi;
      float2 bqv = *reinterpret_cast<const float2*>(bq + h * 32 + c);
      float2 bkv = *reinterpret_cast<const float2*>(bk + h * 32 + c);
      float2 bvv = *reinterpret_cast<const float2*>(bv + h * 32 + c);

      int kbase = nt * 8 + t0;
      KP[row0 * KST + kbase]     = f2tf32(kacc[nt][0] + bkv.x);
      KP[row0 * KST + kbase + 2] = f2tf32(kacc[nt][1] + bkv.y);
      KP[row1 * KST + kbase]     = f2tf32(kacc[nt][2] + bkv.x);
      KP[row1 * KST + kbase + 2] = f2tf32(kacc[nt][3] + bkv.y);

      VP[vp0 + (c << 1)]            = f2tf32(vacc[nt][0] + bvv.x);
      VP[vp0 + ((c + 1) << 1)]      = f2tf32(vacc[nt][1] + bvv.y);
      VP[vp0 + 4 * VST + (c << 1)]       = f2tf32(vacc[nt][2] + bvv.x);
      VP[vp0 + 4 * VST + ((c + 1) << 1)] = f2tf32(vacc[nt][3] + bvv.y);

      c2a((qacc[nt][0] + bqv.x) * scale, (qacc[nt][1] + bqv.y) * scale,
          (qacc[nt][2] + bqv.x) * scale, (qacc[nt][3] + bqv.y) * scale, qa[nt]);
    }
    __syncthreads();

    // ---- streaming attention: S-mma -> exp -> c2a -> PV-mma ----
    float oacc[4][4];
    #pragma unroll
    for (int nt = 0; nt < 4; nt++) {
      oacc[nt][0] = 0.f; oacc[nt][1] = 0.f; oacc[nt][2] = 0.f; oacc[nt][3] = 0.f;
    }
    float sum0 = 0.f, sum1 = 0.f;

    #pragma unroll
    for (int nt = 0; nt < 16; nt++) {
      if (nt <= nt_lim) {
        float s0 = 0.f, s1 = 0.f, s2 = 0.f, s3 = 0.f;
        #pragma unroll
        for (int kt = 0; kt < 4; kt++) {
          uint2 Bk = lds64(KP + (nt * 8 + g) * KST + ((kt * 4 + qi) << 1));
          mma8(s0, s1, s2, s3,
               qa[kt][0], qa[kt][1], qa[kt][2], qa[kt][3], Bk.x, Bk.y);
        }
        int c = nt * 8 + 2 * qi;
        float p0 = (c     > row0) ? 0.f : __expf(s0);
        float p1 = (c + 1 > row0) ? 0.f : __expf(s1);
        float p2 = (c     > row1) ? 0.f : __expf(s2);
        float p3 = (c + 1 > row1) ? 0.f : __expf(s3);
        sum0 += p0 + p1;
        sum1 += p2 + p3;

        uint32_t pa[4];
        c2a(p0, p1, p2, p3, pa);
        int brow = (nt * 4 + qi) * VST;   // token pair (8nt+qi, 8nt+qi+4)
        #pragma unroll
        for (int ntv = 0; ntv < 4; ntv++) {
          uint2 Bv = lds64(VP + brow + ((ntv * 8 + g) << 1));
          mma8(oacc[ntv][0], oacc[ntv][1], oacc[ntv][2], oacc[ntv][3],
               pa[0], pa[1], pa[2], pa[3], Bv.x, Bv.y);
        }
      }
    }

    // row sums (quad reduce), normalize, write O_h into OP (dim pairs)
    sum0 += __shfl_xor_sync(0xffffffffu, sum0, 1);
    sum0 += __shfl_xor_sync(0xffffffffu, sum0, 2);
    sum1 += __shfl_xor_sync(0xffffffffu, sum1, 1);
    sum1 += __shfl_xor_sync(0xffffffffu, sum1, 2);
    float inv0 = __fdividef(1.0f, sum0);
    float inv1 = __fdividef(1.0f, sum1);

    #pragma unroll
    for (int nt = 0; nt < 4; nt++) {
      int base = (h * 4 + nt) * 8 + t0;
      OP[row0 * OST + base]     = f2tf32(oacc[nt][0] * inv0);
      OP[row0 * OST + base + 2] = f2tf32(oacc[nt][1] * inv0);
      OP[row1 * OST + base]     = f2tf32(oacc[nt][2] * inv1);
      OP[row1 * OST + base + 2] = f2tf32(oacc[nt][3] * inv1);
    }
  }  // heads

  // ---- final projection: out = O @ Wp + bp ----
  __syncthreads();  // XP/KP reads done; OP fully written
  {
    uint32_t* WpS = sm;  // reuse XP region (16896 <= 17408 words)
    const float4* wg = reinterpret_cast<const float4*>(Wp);
    #pragma unroll
    for (int i = 0; i < 16; i++) {
      int v = tid + i * 256;
      float4 f = wg[v];
      int d = v >> 5;
      int n0 = (v & 31) << 2;
      int ps = ((d >> 3) << 2) + (d & 3);
      int hf = (d >> 2) & 1;
      uint32_t* p = WpS + ps * PST + (n0 << 1) + hf;
      p[0] = f2tf32(f.x); p[2] = f2tf32(f.y); p[4] = f2tf32(f.z); p[6] = f2tf32(f.w);
    }
    __syncthreads();

    float* og = out + (size_t)b * 16384;
    #pragma unroll
    for (int half = 0; half < 2; half++) {
      float acc[8][4];
      #pragma unroll
      for (int nt8 = 0; nt8 < 8; nt8++) {
        int c = (half * 8 + nt8) * 8 + 2 * qi;
        float2 bpv = *reinterpret_cast<const float2*>(bp + c);
        acc[nt8][0] = bpv.x; acc[nt8][1] = bpv.y;
        acc[nt8][2] = bpv.x; acc[nt8][3] = bpv.y;
      }
      #pragma unroll
      for (int kt = 0; kt < 16; kt++) {
        int acol = (kt * 4 + qi) << 1;
        uint2 A0 = lds64(OP + row0 * OST + acol);
        uint2 A1 = lds64(OP + row1 * OST + acol);
        int brow = (kt * 4 + qi) * PST;
        #pragma unroll
        for (int nt8 = 0; nt8 < 8; nt8++) {
          uint2 B = lds64(WpS + brow + (((half * 8 + nt8) * 8 + g) << 1));
          mma8(acc[nt8][0], acc[nt8][1], acc[nt8][2], acc[nt8][3],
               A0.x, A1.x, A0.y, A1.y, B.x, B.y);
        }
      }
      #pragma unroll
      for (int nt8 = 0; nt8 < 8; nt8++) {
        int c = (half * 8 + nt8) * 8 + 2 * qi;
        *reinterpret_cast<float2*>(og + row0 * 128 + c) = make_float2(acc[nt8][0], acc[nt8][1]);
        *reinterpret_cast<float2*>(og + row1 * 128 + c) = make_float2(acc[nt8][2], acc[nt8][3]);
      }
    }
  }
}

}  // namespace

extern "C" void kernel_launch(void* const* d_in, const int* in_sizes, int n_in,
                              void* d_out, int out_size) {
  const float* x  = (const float*)d_in[0];
  const float* Wq = (const float*)d_in[1];
  const float* bq = (const float*)d_in[2];
  const float* Wk = (const float*)d_in[3];
  const float* bk = (const float*)d_in[4];
  const float* Wv = (const float*)d_in[5];
  const float* bv = (const float*)d_in[6];
  const float* Wp = (const float*)d_in[7];
  const float* bp = (const float*)d_in[8];
  float* out = (float*)d_out;

  int batches = in_sizes[0] / (128 * 128);  // 4096

  cudaFuncSetAttribute(mha_fused_kernel,
                       cudaFuncAttributeMaxDynamicSharedMemorySize, SMEM_BYTES);
  mha_fused_kernel<<<batches, 256, SMEM_BYTES>>>(x, Wq, bq, Wk, bk, Wv, bv, Wp, bp, out);
}

// round 11
// speedup vs baseline: 1.7191x; 1.7191x over previous
#include <cuda_runtime.h>
#include <cstdint>

// ---------------------------------------------------------------------------
// R10: two-kernel split for occupancy.
//  Kernel A (qkv_attn): one CTA per batch element, 2 CTAs/SM.
//    x staged in XOR-swizzled smem; per head: Wq/Wk/Wv staged sequentially in
//    one 128x40 buffer; Q/K/V GEMMs; streaming causal attention; per-head O
//    written to global scratch.
//  Kernel B (proj): out = O @ Wp + bp, tiled tf32 MMA GEMM, 2 CTAs/SM.
// ---------------------------------------------------------------------------

namespace {

// ---- kernel A smem layout (words) ----
constexpr int B1ST = 40;                     // W-stage / V buffer stride
constexpr int B2ST = 36;                     // K buffer stride
constexpr int B1_OFF = 128 * 128;            // after swizzled x (16384 words)
constexpr int B2_OFF = B1_OFF + 128 * B1ST;  // 21504
constexpr int SMEMA_WORDS = B2_OFF + 128 * B2ST;  // 26112 words = 104448 B
constexpr unsigned SMEMA_BYTES = SMEMA_WORDS * 4;

// ---- kernel B smem layout ----
constexpr int WPB_OFF = 128 * 128;                // after swizzled O
constexpr int SMEMB_WORDS = WPB_OFF + 128 * B1ST; // 21504 words = 86016 B
constexpr unsigned SMEMB_BYTES = SMEMB_WORDS * 4;

__device__ float g_scratch[4096ull * 128 * 128];  // 256 MB concat-head output

__device__ __forceinline__ uint32_t f2tf32(float f) {
  uint32_t r;
  asm("cvt.rna.tf32.f32 %0, %1;" : "=r"(r) : "f"(f));
  return r;
}

__device__ __forceinline__ void mma8(float& d0, float& d1, float& d2, float& d3,
                                     uint32_t a0, uint32_t a1, uint32_t a2, uint32_t a3,
                                     uint32_t b0, uint32_t b1) {
  asm volatile(
      "mma.sync.aligned.m16n8k8.row.col.f32.tf32.tf32.f32 "
      "{%0,%1,%2,%3},{%4,%5,%6,%7},{%8,%9},{%0,%1,%2,%3};"
      : "+f"(d0), "+f"(d1), "+f"(d2), "+f"(d3)
      : "r"(a0), "r"(a1), "r"(a2), "r"(a3), "r"(b0), "r"(b1));
}

// m16n8 C-layout tile -> m16k8 A-layout tile (tf32). 8 shuffles, warp-uniform.
__device__ __forceinline__ void c2a(float c0, float c1, float c2, float c3,
                                    uint32_t a[4]) {
  int lane = threadIdx.x & 31;
  int qi = lane & 3;
  int s1 = (lane & ~3) | (qi >> 1);
  int s2 = s1 + 2;
  float t0 = __shfl_sync(0xffffffffu, c0, s1);
  float t1 = __shfl_sync(0xffffffffu, c1, s1);
  float t2 = __shfl_sync(0xffffffffu, c2, s1);
  float t3 = __shfl_sync(0xffffffffu, c3, s1);
  float u0 = __shfl_sync(0xffffffffu, c0, s2);
  float u1 = __shfl_sync(0xffffffffu, c1, s2);
  float u2 = __shfl_sync(0xffffffffu, c2, s2);
  float u3 = __shfl_sync(0xffffffffu, c3, s2);
  bool odd = (qi & 1);
  a[0] = f2tf32(odd ? t1 : t0);
  a[1] = f2tf32(odd ? t3 : t2);
  a[2] = f2tf32(odd ? u1 : u0);
  a[3] = f2tf32(odd ? u3 : u2);
}

// Stage a [128 tokens/rows x 128 dims] fp32 matrix into XOR-swizzled tf32 smem.
// word(t, d) = t*128 + (d ^ ((t&7)<<2)).  A-frag reads are conflict-free.
__device__ __forceinline__ void stage_sw128(uint32_t* dst, const float* src, int tid) {
  const float4* s4 = reinterpret_cast<const float4*>(src);
  #pragma unroll
  for (int i = 0; i < 16; i++) {
    int v = tid + i * 256;
    float4 f = s4[v];
    int t = v >> 5;
    int d0 = (v & 31) << 2;
    uint32_t* p = dst + t * 128 + (d0 ^ ((t & 7) << 2));
    p[0] = f2tf32(f.x); p[1] = f2tf32(f.y); p[2] = f2tf32(f.z); p[3] = f2tf32(f.w);
  }
}

// Stage one [128 x 32] fp32 weight matrix into smem, row stride 40 (tf32).
__device__ __forceinline__ void stage_w(uint32_t* dst, const float* src, int tid) {
  const float4* s4 = reinterpret_cast<const float4*>(src);
  #pragma unroll
  for (int i = 0; i < 4; i++) {
    int v = tid + i * 256;
    float4 f = s4[v];
    int d = v >> 3;
    int n0 = (v & 7) << 2;
    uint32_t* p = dst + d * B1ST + n0;
    p[0] = f2tf32(f.x); p[1] = f2tf32(f.y); p[2] = f2tf32(f.z); p[3] = f2tf32(f.w);
  }
}

// acc[4][4] += XS(16 rows of warp) @ Wbuf(128x32, stride 40)
__device__ __forceinline__ void gemm_x_w(const uint32_t* XS, const uint32_t* Wb,
                                         int xr0, int xr1, int xsw, int qi, int g,
                                         float acc[4][4]) {
  #pragma unroll
  for (int kt = 0; kt < 16; kt++) {
    int c = kt * 8 + qi;
    uint32_t a0 = XS[xr0 + (c ^ xsw)];
    uint32_t a1 = XS[xr1 + (c ^ xsw)];
    uint32_t a2 = XS[xr0 + ((c + 4) ^ xsw)];
    uint32_t a3 = XS[xr1 + ((c + 4) ^ xsw)];
    int brow = c * B1ST;
    #pragma unroll
    for (int nt = 0; nt < 4; nt++) {
      int boff = brow + nt * 8 + g;
      mma8(acc[nt][0], acc[nt][1], acc[nt][2], acc[nt][3],
           a0, a1, a2, a3, Wb[boff], Wb[boff + 4 * B1ST]);
    }
  }
}

// ============================ Kernel A ====================================
__global__ __launch_bounds__(256, 2)
void qkv_attn_kernel(const float* __restrict__ x,
                     const float* __restrict__ Wq, const float* __restrict__ bq,
                     const float* __restrict__ Wk, const float* __restrict__ bk,
                     const float* __restrict__ Wv, const float* __restrict__ bv) {
  extern __shared__ uint32_t sm[];
  uint32_t* XS = sm;
  uint32_t* B1 = sm + B1_OFF;   // W stage, later V (token-major, stride 40)
  uint32_t* B2 = sm + B2_OFF;   // K (token-major, stride 36)

  const int tid = threadIdx.x;
  const int lane = tid & 31;
  const int w = tid >> 5;
  const int g = lane >> 2;
  const int qi = lane & 3;
  const int b = blockIdx.x;
  const int row0 = w * 16 + g;
  const int row1 = row0 + 8;
  const int xr0 = row0 * 128, xr1 = row1 * 128, xsw = g << 2;

  stage_sw128(XS, x + (size_t)b * 16384, tid);

  const int nt_lim = 2 * w + 1;
  const float scale = 0.088388347648318447f;  // 128^-0.5 (CONTEXT_SIZE scaling)
  float* og = g_scratch + (size_t)b * 16384;

  for (int h = 0; h < 4; h++) {
    __syncthreads();  // XS staged / prior head's B1(V),B2(K) reads done

    // ---- Q = x @ Wq_h ----
    stage_w(B1, Wq + h * 4096, tid);
    __syncthreads();
    float acc[4][4];
    #pragma unroll
    for (int nt = 0; nt < 4; nt++)
      { acc[nt][0] = 0.f; acc[nt][1] = 0.f; acc[nt][2] = 0.f; acc[nt][3] = 0.f; }
    gemm_x_w(XS, B1, xr0, xr1, xsw, qi, g, acc);
    uint32_t qa[4][4];
    #pragma unroll
    for (int nt = 0; nt < 4; nt++) {
      int c = nt * 8 + 2 * qi;
      float2 bv2 = *reinterpret_cast<const float2*>(bq + h * 32 + c);
      c2a((acc[nt][0] + bv2.x) * scale, (acc[nt][1] + bv2.y) * scale,
          (acc[nt][2] + bv2.x) * scale, (acc[nt][3] + bv2.y) * scale, qa[nt]);
    }
    __syncthreads();

    // ---- K = x @ Wk_h ----
    stage_w(B1, Wk + h * 4096, tid);
    __syncthreads();
    #pragma unroll
    for (int nt = 0; nt < 4; nt++)
      { acc[nt][0] = 0.f; acc[nt][1] = 0.f; acc[nt][2] = 0.f; acc[nt][3] = 0.f; }
    gemm_x_w(XS, B1, xr0, xr1, xsw, qi, g, acc);
    __syncthreads();  // B1 reads done before Wv overwrites; B2 free
    #pragma unroll
    for (int nt = 0; nt < 4; nt++) {
      int c = nt * 8 + 2 * qi;
      float2 bv2 = *reinterpret_cast<const float2*>(bk + h * 32 + c);
      B2[row0 * B2ST + c]     = f2tf32(acc[nt][0] + bv2.x);
      B2[row0 * B2ST + c + 1] = f2tf32(acc[nt][1] + bv2.y);
      B2[row1 * B2ST + c]     = f2tf32(acc[nt][2] + bv2.x);
      B2[row1 * B2ST + c + 1] = f2tf32(acc[nt][3] + bv2.y);
    }

    // ---- V = x @ Wv_h ----
    stage_w(B1, Wv + h * 4096, tid);
    __syncthreads();
    #pragma unroll
    for (int nt = 0; nt < 4; nt++)
      { acc[nt][0] = 0.f; acc[nt][1] = 0.f; acc[nt][2] = 0.f; acc[nt][3] = 0.f; }
    gemm_x_w(XS, B1, xr0, xr1, xsw, qi, g, acc);
    __syncthreads();  // Wv reads done; store V into B1
    #pragma unroll
    for (int nt = 0; nt < 4; nt++) {
      int c = nt * 8 + 2 * qi;
      float2 bv2 = *reinterpret_cast<const float2*>(bv + h * 32 + c);
      B1[row0 * B1ST + c]     = f2tf32(acc[nt][0] + bv2.x);
      B1[row0 * B1ST + c + 1] = f2tf32(acc[nt][1] + bv2.y);
      B1[row1 * B1ST + c]     = f2tf32(acc[nt][2] + bv2.x);
      B1[row1 * B1ST + c + 1] = f2tf32(acc[nt][3] + bv2.y);
    }
    __syncthreads();  // K (B2) and V (B1) visible

    // ---- streaming causal attention ----
    float oacc[4][4];
    #pragma unroll
    for (int nt = 0; nt < 4; nt++)
      { oacc[nt][0] = 0.f; oacc[nt][1] = 0.f; oacc[nt][2] = 0.f; oacc[nt][3] = 0.f; }
    float sum0 = 0.f, sum1 = 0.f;

    #pragma unroll
    for (int nt = 0; nt < 16; nt++) {
      if (nt <= nt_lim) {
        float s0 = 0.f, s1 = 0.f, s2 = 0.f, s3 = 0.f;
        #pragma unroll
        for (int kt = 0; kt < 4; kt++) {
          int boff = (nt * 8 + g) * B2ST + kt * 8 + qi;
          mma8(s0, s1, s2, s3,
               qa[kt][0], qa[kt][1], qa[kt][2], qa[kt][3],
               B2[boff], B2[boff + 4]);
        }
        int c = nt * 8 + 2 * qi;
        float p0 = (c     > row0) ? 0.f : __expf(s0);
        float p1 = (c + 1 > row0) ? 0.f : __expf(s1);
        float p2 = (c     > row1) ? 0.f : __expf(s2);
        float p3 = (c + 1 > row1) ? 0.f : __expf(s3);
        sum0 += p0 + p1;
        sum1 += p2 + p3;

        uint32_t pa[4];
        c2a(p0, p1, p2, p3, pa);
        int brow = (nt * 8 + qi) * B1ST;
        #pragma unroll
        for (int ntv = 0; ntv < 4; ntv++) {
          int boff = brow + ntv * 8 + g;
          mma8(oacc[ntv][0], oacc[ntv][1], oacc[ntv][2], oacc[ntv][3],
               pa[0], pa[1], pa[2], pa[3], B1[boff], B1[boff + 4 * B1ST]);
        }
      }
    }

    sum0 += __shfl_xor_sync(0xffffffffu, sum0, 1);
    sum0 += __shfl_xor_sync(0xffffffffu, sum0, 2);
    sum1 += __shfl_xor_sync(0xffffffffu, sum1, 1);
    sum1 += __shfl_xor_sync(0xffffffffu, sum1, 2);
    float inv0 = __fdividef(1.0f, sum0);
    float inv1 = __fdividef(1.0f, sum1);

    #pragma unroll
    for (int nt = 0; nt < 4; nt++) {
      int c = h * 32 + nt * 8 + 2 * qi;
      *reinterpret_cast<float2*>(og + row0 * 128 + c) =
          make_float2(oacc[nt][0] * inv0, oacc[nt][1] * inv0);
      *reinterpret_cast<float2*>(og + row1 * 128 + c) =
          make_float2(oacc[nt][2] * inv1, oacc[nt][3] * inv1);
    }
  }
}

// ============================ Kernel B ====================================
// out = O @ Wp + bp.  One CTA per batch element; Wp staged in 32-col chunks.
__global__ __launch_bounds__(256, 2)
void proj_kernel(const float* __restrict__ Wp, const float* __restrict__ bp,
                 float* __restrict__ out) {
  extern __shared__ uint32_t sm[];
  uint32_t* OS = sm;
  uint32_t* WB = sm + WPB_OFF;

  const int tid = threadIdx.x;
  const int lane = tid & 31;
  const int w = tid >> 5;
  const int g = lane >> 2;
  const int qi = lane & 3;
  const int b = blockIdx.x;
  const int row0 = w * 16 + g;
  const int row1 = row0 + 8;
  const int xr0 = row0 * 128, xr1 = row1 * 128, xsw = g << 2;

  stage_sw128(OS, g_scratch + (size_t)b * 16384, tid);

  float* og = out + (size_t)b * 16384;

  #pragma unroll
  for (int c32 = 0; c32 < 4; c32++) {
    __syncthreads();  // OS staged / prior WB reads done
    // stage Wp[:, 32*c32 .. +32) -> WB (stride 40)
    #pragma unroll
    for (int i = 0; i < 4; i++) {
      int v = tid + i * 256;
      int d = v >> 3;
      int n0 = (v & 7) << 2;
      float4 f = *reinterpret_cast<const float4*>(Wp + d * 128 + c32 * 32 + n0);
      uint32_t* p = WB + d * B1ST + n0;
      p[0] = f2tf32(f.x); p[1] = f2tf32(f.y); p[2] = f2tf32(f.z); p[3] = f2tf32(f.w);
    }
    __syncthreads();

    float acc[4][4];
    #pragma unroll
    for (int nt = 0; nt < 4; nt++) {
      int c = c32 * 32 + nt * 8 + 2 * qi;
      float2 bp2 = *reinterpret_cast<const float2*>(bp + c);
      acc[nt][0] = bp2.x; acc[nt][1] = bp2.y; acc[nt][2] = bp2.x; acc[nt][3] = bp2.y;
    }
    gemm_x_w(OS, WB, xr0, xr1, xsw, qi, g, acc);

    #pragma unroll
    for (int nt = 0; nt < 4; nt++) {
      int c = c32 * 32 + nt * 8 + 2 * qi;
      *reinterpret_cast<float2*>(og + row0 * 128 + c) = make_float2(acc[nt][0], acc[nt][1]);
      *reinterpret_cast<float2*>(og + row1 * 128 + c) = make_float2(acc[nt][2], acc[nt][3]);
    }
  }
}

}  // namespace

extern "C" void kernel_launch(void* const* d_in, const int* in_sizes, int n_in,
                              void* d_out, int out_size) {
  const float* x  = (const float*)d_in[0];
  const float* Wq = (const float*)d_in[1];
  const float* bq = (const float*)d_in[2];
  const float* Wk = (const float*)d_in[3];
  const float* bk = (const float*)d_in[4];
  const float* Wv = (const float*)d_in[5];
  const float* bv = (const float*)d_in[6];
  const float* Wp = (const float*)d_in[7];
  const float* bp = (const float*)d_in[8];
  float* out = (float*)d_out;

  int batches = in_sizes[0] / (128 * 128);  // 4096

  cudaFuncSetAttribute(qkv_attn_kernel,
                       cudaFuncAttributeMaxDynamicSharedMemorySize, SMEMA_BYTES);
  cudaFuncSetAttribute(proj_kernel,
                       cudaFuncAttributeMaxDynamicSharedMemorySize, SMEMB_BYTES);

  qkv_attn_kernel<<<batches, 256, SMEMA_BYTES>>>(x, Wq, bq, Wk, bk, Wv, bv);
  proj_kernel<<<batches, 256, SMEMB_BYTES>>>(Wp, bp, out);
}

// round 12
// speedup vs baseline: 1.8452x; 1.0733x over previous
#include <cuda_runtime.h>
#include <cstdint>

// ---------------------------------------------------------------------------
// R11: two-kernel split, improved.
//  Kernel A (qkv_attn): one CTA per batch element, 2 CTAs/SM.
//    Double-buffered weight staging (Wk staged during Q-GEMM, Wv during
//    K-GEMM); K stored into the dead Wk buffer with an XOR swizzle
//    (conflict-free stores AND S-GEMM loads); 6 syncthreads/head.
//    Per-head O is c2a'd to tf32 A-fragments and written coalesced (STG.128)
//    to scratch in thread-linear fragment order.
//  Kernel B (proj): A-frags loaded directly from scratch via 16x LDG.128
//    (no O smem, no re-reads); Wp staged once at stride 136; out = O@Wp + bp.
// ---------------------------------------------------------------------------

namespace {

constexpr int WAST = 40;                       // W/V/K buffer stride (words)
constexpr int B1A_OFF = 128 * 128;             // after swizzled x (16384 words)
constexpr int B1B_OFF = B1A_OFF + 128 * WAST;  // 21504
constexpr int SMEMA_WORDS = B1B_OFF + 128 * WAST;  // 26624 words = 106496 B
constexpr unsigned SMEMA_BYTES = SMEMA_WORDS * 4;

constexpr int PST = 136;                        // Wp stage stride (proj)
constexpr int SMEMB_WORDS = 128 * PST;          // 17408 words = 69632 B
constexpr unsigned SMEMB_BYTES = SMEMB_WORDS * 4;

// O scratch in tf32 A-fragment order: [(b*8+w)*16 + kt][lane*4 + j]
__device__ uint32_t g_scratch[4096ull * 16 * 8 * 128];

__device__ __forceinline__ uint32_t f2tf32(float f) {
  uint32_t r;
  asm("cvt.rna.tf32.f32 %0, %1;" : "=r"(r) : "f"(f));
  return r;
}

__device__ __forceinline__ void mma8(float& d0, float& d1, float& d2, float& d3,
                                     uint32_t a0, uint32_t a1, uint32_t a2, uint32_t a3,
                                     uint32_t b0, uint32_t b1) {
  asm volatile(
      "mma.sync.aligned.m16n8k8.row.col.f32.tf32.tf32.f32 "
      "{%0,%1,%2,%3},{%4,%5,%6,%7},{%8,%9},{%0,%1,%2,%3};"
      : "+f"(d0), "+f"(d1), "+f"(d2), "+f"(d3)
      : "r"(a0), "r"(a1), "r"(a2), "r"(a3), "r"(b0), "r"(b1));
}

// m16n8 C-layout tile -> m16k8 A-layout tile (tf32). 8 shuffles, warp-uniform.
__device__ __forceinline__ void c2a(float c0, float c1, float c2, float c3,
                                    uint32_t a[4]) {
  int lane = threadIdx.x & 31;
  int qi = lane & 3;
  int s1 = (lane & ~3) | (qi >> 1);
  int s2 = s1 + 2;
  float t0 = __shfl_sync(0xffffffffu, c0, s1);
  float t1 = __shfl_sync(0xffffffffu, c1, s1);
  float t2 = __shfl_sync(0xffffffffu, c2, s1);
  float t3 = __shfl_sync(0xffffffffu, c3, s1);
  float u0 = __shfl_sync(0xffffffffu, c0, s2);
  float u1 = __shfl_sync(0xffffffffu, c1, s2);
  float u2 = __shfl_sync(0xffffffffu, c2, s2);
  float u3 = __shfl_sync(0xffffffffu, c3, s2);
  bool odd = (qi & 1);
  a[0] = f2tf32(odd ? t1 : t0);
  a[1] = f2tf32(odd ? t3 : t2);
  a[2] = f2tf32(odd ? u1 : u0);
  a[3] = f2tf32(odd ? u3 : u2);
}

// Stage [128 x 128] fp32 -> XOR-swizzled tf32 smem. word(t,d)=t*128+(d^((t&7)<<2))
__device__ __forceinline__ void stage_sw128(uint32_t* dst, const float* src, int tid) {
  const float4* s4 = reinterpret_cast<const float4*>(src);
  #pragma unroll
  for (int i = 0; i < 16; i++) {
    int v = tid + i * 256;
    float4 f = s4[v];
    int t = v >> 5;
    int d0 = (v & 31) << 2;
    uint32_t* p = dst + t * 128 + (d0 ^ ((t & 7) << 2));
    p[0] = f2tf32(f.x); p[1] = f2tf32(f.y); p[2] = f2tf32(f.z); p[3] = f2tf32(f.w);
  }
}

// Stage one [128 x 32] fp32 weight matrix into smem, row stride 40 (tf32).
__device__ __forceinline__ void stage_w(uint32_t* dst, const float* src, int tid) {
  const float4* s4 = reinterpret_cast<const float4*>(src);
  #pragma unroll
  for (int i = 0; i < 4; i++) {
    int v = tid + i * 256;
    float4 f = s4[v];
    uint32_t* p = dst + (v >> 3) * WAST + ((v & 7) << 2);
    p[0] = f2tf32(f.x); p[1] = f2tf32(f.y); p[2] = f2tf32(f.z); p[3] = f2tf32(f.w);
  }
}

// acc[4][4] += XS(16 rows of warp) @ Wbuf(128x32, stride 40)
__device__ __forceinline__ void gemm_x_w(const uint32_t* XS, const uint32_t* Wb,
                                         int xr0, int xr1, int xsw, int qi, int g,
                                         float acc[4][4]) {
  #pragma unroll
  for (int kt = 0; kt < 16; kt++) {
    int c = kt * 8 + qi;
    uint32_t a0 = XS[xr0 + (c ^ xsw)];
    uint32_t a1 = XS[xr1 + (c ^ xsw)];
    uint32_t a2 = XS[xr0 + ((c + 4) ^ xsw)];
    uint32_t a3 = XS[xr1 + ((c + 4) ^ xsw)];
    int brow = c * WAST;
    #pragma unroll
    for (int nt = 0; nt < 4; nt++) {
      int boff = brow + nt * 8 + g;
      mma8(acc[nt][0], acc[nt][1], acc[nt][2], acc[nt][3],
           a0, a1, a2, a3, Wb[boff], Wb[boff + 4 * WAST]);
    }
  }
}

// ============================ Kernel A ====================================
__global__ __launch_bounds__(256, 2)
void qkv_attn_kernel(const float* __restrict__ x,
                     const float* __restrict__ Wq, const float* __restrict__ bq,
                     const float* __restrict__ Wk, const float* __restrict__ bk,
                     const float* __restrict__ Wv, const float* __restrict__ bv) {
  extern __shared__ uint32_t sm[];
  uint32_t* XS = sm;
  uint32_t* BA = sm + B1A_OFF;   // Wq stage -> Wv stage -> V
  uint32_t* BB = sm + B1B_OFF;   // Wk stage -> K (XOR-swizzled)

  const int tid = threadIdx.x;
  const int lane = tid & 31;
  const int w = tid >> 5;
  const int g = lane >> 2;
  const int qi = lane & 3;
  const int b = blockIdx.x;
  const int row0 = w * 16 + g;
  const int row1 = row0 + 8;
  const int xr0 = row0 * 128, xr1 = row1 * 128, xsw = g << 2;
  const int ksw = g << 2;   // K swizzle: row&7 == g for rows 16w+g and +8

  stage_sw128(XS, x + (size_t)b * 16384, tid);

  const int nt_lim = 2 * w + 1;
  const float scale = 0.088388347648318447f;  // 128^-0.5 (CONTEXT_SIZE scaling)
  uint32_t* og = g_scratch + ((size_t)b * 8 + w) * 2048 + lane * 4;

  for (int h = 0; h < 4; h++) {
    __syncthreads();                       // sync0: prior attention K/V reads done

    stage_w(BA, Wq + h * 4096, tid);
    __syncthreads();                       // sync1: Wq visible

    // ---- Q = x @ Wq_h ----
    float acc[4][4];
    #pragma unroll
    for (int nt = 0; nt < 4; nt++)
      { acc[nt][0] = 0.f; acc[nt][1] = 0.f; acc[nt][2] = 0.f; acc[nt][3] = 0.f; }
    gemm_x_w(XS, BA, xr0, xr1, xsw, qi, g, acc);
    uint32_t qa[4][4];
    #pragma unroll
    for (int nt = 0; nt < 4; nt++) {
      int c = nt * 8 + 2 * qi;
      float2 b2 = *reinterpret_cast<const float2*>(bq + h * 32 + c);
      c2a((acc[nt][0] + b2.x) * scale, (acc[nt][1] + b2.y) * scale,
          (acc[nt][2] + b2.x) * scale, (acc[nt][3] + b2.y) * scale, qa[nt]);
    }
    stage_w(BB, Wk + h * 4096, tid);       // overlap: Wk stage after Q-GEMM
    __syncthreads();                       // sync2: Wk visible, all Q-GEMMs done

    // ---- K = x @ Wk_h ----
    #pragma unroll
    for (int nt = 0; nt < 4; nt++)
      { acc[nt][0] = 0.f; acc[nt][1] = 0.f; acc[nt][2] = 0.f; acc[nt][3] = 0.f; }
    gemm_x_w(XS, BB, xr0, xr1, xsw, qi, g, acc);
    float kv[4][4];
    #pragma unroll
    for (int nt = 0; nt < 4; nt++) {
      int c = nt * 8 + 2 * qi;
      float2 b2 = *reinterpret_cast<const float2*>(bk + h * 32 + c);
      kv[nt][0] = acc[nt][0] + b2.x; kv[nt][1] = acc[nt][1] + b2.y;
      kv[nt][2] = acc[nt][2] + b2.x; kv[nt][3] = acc[nt][3] + b2.y;
    }
    stage_w(BA, Wv + h * 4096, tid);       // overlap: Wv stage (Wq dead)
    __syncthreads();                       // sync3: Wv visible, all K-GEMMs done

    // ---- V = x @ Wv_h ----
    #pragma unroll
    for (int nt = 0; nt < 4; nt++)
      { acc[nt][0] = 0.f; acc[nt][1] = 0.f; acc[nt][2] = 0.f; acc[nt][3] = 0.f; }
    gemm_x_w(XS, BA, xr0, xr1, xsw, qi, g, acc);
    // store K into BB (Wk dead; all K-GEMM reads finished at sync3), swizzled
    #pragma unroll
    for (int nt = 0; nt < 4; nt++) {
      int c = nt * 8 + 2 * qi;
      BB[row0 * WAST + (c ^ ksw)]       = f2tf32(kv[nt][0]);
      BB[row0 * WAST + ((c + 1) ^ ksw)] = f2tf32(kv[nt][1]);
      BB[row1 * WAST + (c ^ ksw)]       = f2tf32(kv[nt][2]);
      BB[row1 * WAST + ((c + 1) ^ ksw)] = f2tf32(kv[nt][3]);
    }
    __syncthreads();                       // sync4: all V-GEMMs done (Wv dead)
    // store V into BA
    #pragma unroll
    for (int nt = 0; nt < 4; nt++) {
      int c = nt * 8 + 2 * qi;
      float2 b2 = *reinterpret_cast<const float2*>(bv + h * 32 + c);
      BA[row0 * WAST + c]     = f2tf32(acc[nt][0] + b2.x);
      BA[row0 * WAST + c + 1] = f2tf32(acc[nt][1] + b2.y);
      BA[row1 * WAST + c]     = f2tf32(acc[nt][2] + b2.x);
      BA[row1 * WAST + c + 1] = f2tf32(acc[nt][3] + b2.y);
    }
    __syncthreads();                       // sync5: K (BB) and V (BA) visible

    // ---- streaming causal attention ----
    float oacc[4][4];
    #pragma unroll
    for (int nt = 0; nt < 4; nt++)
      { oacc[nt][0] = 0.f; oacc[nt][1] = 0.f; oacc[nt][2] = 0.f; oacc[nt][3] = 0.f; }
    float sum0 = 0.f, sum1 = 0.f;

    #pragma unroll
    for (int nt = 0; nt < 16; nt++) {
      if (nt <= nt_lim) {
        float s0 = 0.f, s1 = 0.f, s2 = 0.f, s3 = 0.f;
        int krow = (nt * 8 + g) * WAST;
        #pragma unroll
        for (int kt = 0; kt < 4; kt++) {
          uint32_t b0 = BB[krow + ((kt * 8 + qi) ^ ksw)];
          uint32_t b1 = BB[krow + ((kt * 8 + qi + 4) ^ ksw)];
          mma8(s0, s1, s2, s3,
               qa[kt][0], qa[kt][1], qa[kt][2], qa[kt][3], b0, b1);
        }
        int c = nt * 8 + 2 * qi;
        float p0 = (c     > row0) ? 0.f : __expf(s0);
        float p1 = (c + 1 > row0) ? 0.f : __expf(s1);
        float p2 = (c     > row1) ? 0.f : __expf(s2);
        float p3 = (c + 1 > row1) ? 0.f : __expf(s3);
        sum0 += p0 + p1;
        sum1 += p2 + p3;

        uint32_t pa[4];
        c2a(p0, p1, p2, p3, pa);
        int brow = (nt * 8 + qi) * WAST;
        #pragma unroll
        for (int ntv = 0; ntv < 4; ntv++) {
          int boff = brow + ntv * 8 + g;
          mma8(oacc[ntv][0], oacc[ntv][1], oacc[ntv][2], oacc[ntv][3],
               pa[0], pa[1], pa[2], pa[3], BA[boff], BA[boff + 4 * WAST]);
        }
      }
    }

    sum0 += __shfl_xor_sync(0xffffffffu, sum0, 1);
    sum0 += __shfl_xor_sync(0xffffffffu, sum0, 2);
    sum1 += __shfl_xor_sync(0xffffffffu, sum1, 1);
    sum1 += __shfl_xor_sync(0xffffffffu, sum1, 2);
    float inv0 = __fdividef(1.0f, sum0);
    float inv1 = __fdividef(1.0f, sum1);

    // normalize -> A-layout tf32 -> coalesced STG.128 to scratch
    #pragma unroll
    for (int nt = 0; nt < 4; nt++) {
      uint32_t oa[4];
      c2a(oacc[nt][0] * inv0, oacc[nt][1] * inv0,
          oacc[nt][2] * inv1, oacc[nt][3] * inv1, oa);
      *reinterpret_cast<uint4*>(og + (h * 4 + nt) * 128) =
          make_uint4(oa[0], oa[1], oa[2], oa[3]);
    }
  }
}

// ============================ Kernel B ====================================
// out = O @ Wp + bp.  A-frags straight from scratch via LDG.128; Wp staged once.
__global__ __launch_bounds__(256, 2)
void proj_kernel(const float* __restrict__ Wp, const float* __restrict__ bp,
                 float* __restrict__ out) {
  extern __shared__ uint32_t sm[];   // Wp, stride 136

  const int tid = threadIdx.x;
  const int lane = tid & 31;
  const int w = tid >> 5;
  const int g = lane >> 2;
  const int qi = lane & 3;
  const int b = blockIdx.x;
  const int row0 = w * 16 + g;
  const int row1 = row0 + 8;

  // stage Wp (tf32, stride 136)
  {
    const float4* wg = reinterpret_cast<const float4*>(Wp);
    #pragma unroll
    for (int i = 0; i < 16; i++) {
      int v = tid + i * 256;
      float4 f = wg[v];
      uint32_t* p = sm + (v >> 5) * PST + ((v & 31) << 2);
      p[0] = f2tf32(f.x); p[1] = f2tf32(f.y); p[2] = f2tf32(f.z); p[3] = f2tf32(f.w);
    }
  }

  // A-frags: 16 coalesced LDG.128 from scratch
  uint32_t A[16][4];
  const uint32_t* ab = g_scratch + ((size_t)b * 8 + w) * 2048 + lane * 4;
  #pragma unroll
  for (int kt = 0; kt < 16; kt++) {
    uint4 v = *reinterpret_cast<const uint4*>(ab + kt * 128);
    A[kt][0] = v.x; A[kt][1] = v.y; A[kt][2] = v.z; A[kt][3] = v.w;
  }
  __syncthreads();

  float* og = out + (size_t)b * 16384;
  #pragma unroll
  for (int half = 0; half < 2; half++) {
    float acc[8][4];
    #pragma unroll
    for (int nt8 = 0; nt8 < 8; nt8++) {
      int c = (half * 8 + nt8) * 8 + 2 * qi;
      float2 bp2 = *reinterpret_cast<const float2*>(bp + c);
      acc[nt8][0] = bp2.x; acc[nt8][1] = bp2.y; acc[nt8][2] = bp2.x; acc[nt8][3] = bp2.y;
    }
    #pragma unroll
    for (int kt = 0; kt < 16; kt++) {
      int brow = (kt * 8 + qi) * PST;
      #pragma unroll
      for (int nt8 = 0; nt8 < 8; nt8++) {
        int boff = brow + (half * 8 + nt8) * 8 + g;
        mma8(acc[nt8][0], acc[nt8][1], acc[nt8][2], acc[nt8][3],
             A[kt][0], A[kt][1], A[kt][2], A[kt][3],
             sm[boff], sm[boff + 4 * PST]);
      }
    }
    #pragma unroll
    for (int nt8 = 0; nt8 < 8; nt8++) {
      int c = (half * 8 + nt8) * 8 + 2 * qi;
      *reinterpret_cast<float2*>(og + row0 * 128 + c) = make_float2(acc[nt8][0], acc[nt8][1]);
      *reinterpret_cast<float2*>(og + row1 * 128 + c) = make_float2(acc[nt8][2], acc[nt8][3]);
    }
  }
}

}  // namespace

extern "C" void kernel_launch(void* const* d_in, const int* in_sizes, int n_in,
                              void* d_out, int out_size) {
  const float* x  = (const float*)d_in[0];
  const float* Wq = (const float*)d_in[1];
  const float* bq = (const float*)d_in[2];
  const float* Wk = (const float*)d_in[3];
  const float* bk = (const float*)d_in[4];
  const float* Wv = (const float*)d_in[5];
  const float* bv = (const float*)d_in[6];
  const float* Wp = (const float*)d_in[7];
  const float* bp = (const float*)d_in[8];
  float* out = (float*)d_out;

  int batches = in_sizes[0] / (128 * 128);  // 4096

  cudaFuncSetAttribute(qkv_attn_kernel,
                       cudaFuncAttributeMaxDynamicSharedMemorySize, SMEMA_BYTES);
  cudaFuncSetAttribute(proj_kernel,
                       cudaFuncAttributeMaxDynamicSharedMemorySize, SMEMB_BYTES);

  qkv_attn_kernel<<<batches, 256, SMEMA_BYTES>>>(x, Wq, bq, Wk, bk, Wv, bv);
  proj_kernel<<<batches, 256, SMEMB_BYTES>>>(Wp, bp, out);
}